// round 1
// baseline (speedup 1.0000x reference)
#include <cuda_runtime.h>
#include <math.h>

#define NNODE 10000
#define NEDGE 320000
#define ETOT  (NEDGE + NNODE)
#define FIN   256
#define HH    8
#define CC    64
#define FOUT  512   /* HH*CC */
#define NEG   0.2f

// ---------------- static device scratch (no allocations allowed) ------------
__device__ float g_h[NNODE * FOUT];       // per-layer GEMM output  (20.5 MB)
__device__ float g_x2[NNODE * FOUT];      // layer-1 activated output (20.5 MB)
__device__ float g_als[NNODE * HH];
__device__ float g_ald[NNODE * HH];
__device__ float g_alpha[ETOT * HH];      // per-(edge,head) attn scratch (10.6 MB)
__device__ float g_rden[NNODE * HH];      // 1/softmax-denominator
__device__ int   g_cnt[NNODE];
__device__ int   g_offs[NNODE + 1];
__device__ int   g_cursor[NNODE];
__device__ int   g_srcs[ETOT];            // dst-sorted CSR: src per slot
__device__ float g_lew[ETOT];             // dst-sorted CSR: log2(edge_weight)

// ---------------- CSR build -------------------------------------------------
__global__ void k_zero_cnt() {
    int i = blockIdx.x * blockDim.x + threadIdx.x;
    if (i < NNODE) g_cnt[i] = 0;
}

__global__ void k_hist(const int* __restrict__ ei) {
    int e = blockIdx.x * blockDim.x + threadIdx.x;
    if (e >= ETOT) return;
    int d = (e < NEDGE) ? ei[NEDGE + e] : (e - NEDGE);
    atomicAdd(&g_cnt[d], 1);
}

__global__ void k_scan() {
    __shared__ int sh[1024];
    int t = threadIdx.x;
    const int CH = (NNODE + 1023) / 1024;   // 10
    int base = t * CH;
    int s = 0;
    for (int i = 0; i < CH; i++) {
        int idx = base + i;
        if (idx < NNODE) s += g_cnt[idx];
    }
    sh[t] = s;
    __syncthreads();
    for (int off = 1; off < 1024; off <<= 1) {
        int v = (t >= off) ? sh[t - off] : 0;
        __syncthreads();
        sh[t] += v;
        __syncthreads();
    }
    int run = (t == 0) ? 0 : sh[t - 1];
    for (int i = 0; i < CH; i++) {
        int idx = base + i;
        if (idx < NNODE) {
            g_offs[idx]   = run;
            g_cursor[idx] = run;
            run += g_cnt[idx];
        }
    }
    if (t == 1023) g_offs[NNODE] = run;
}

__global__ void k_scatter(const int* __restrict__ ei, const float* __restrict__ ew) {
    int e = blockIdx.x * blockDim.x + threadIdx.x;
    if (e >= ETOT) return;
    int s, d; float lw;
    if (e < NEDGE) {
        s = ei[e]; d = ei[NEDGE + e];
        lw = log2f(ew[e]);
    } else {
        s = d = e - NEDGE;
        lw = 0.f;
    }
    int pos = atomicAdd(&g_cursor[d], 1);
    g_srcs[pos] = s;
    g_lew[pos]  = lw;
}

// ---------------- fp32 SGEMM: C[M,512] = A[M,K] @ B[K,512] ------------------
// 128x128 block tile, TK=8, 256 threads, 8x8 micro-tile per thread.
__global__ __launch_bounds__(256) void k_sgemm(
    const float* __restrict__ A_ext, const float* __restrict__ B,
    int M, int K, int a_internal)
{
    __shared__ __align__(16) float As[8][132];   // pitch 132 -> conflict-free STS
    __shared__ __align__(16) float Bs[8][128];
    const int NN = FOUT;
    const float* A = a_internal ? g_x2 : A_ext;

    int bm = blockIdx.y * 128;
    int bn = blockIdx.x * 128;
    int tid = threadIdx.x;
    int am = tid >> 1, ak = (tid & 1) * 4;
    int bk = tid >> 5, bnn = (tid & 31) * 4;
    int tx = tid & 15, ty = tid >> 4;

    float acc[8][8];
#pragma unroll
    for (int i = 0; i < 8; i++)
#pragma unroll
        for (int j = 0; j < 8; j++) acc[i][j] = 0.f;

    for (int k0 = 0; k0 < K; k0 += 8) {
        int row = bm + am;
        float4 av = (row < M)
            ? *(const float4*)(A + (size_t)row * K + k0 + ak)
            : make_float4(0.f, 0.f, 0.f, 0.f);
        As[ak + 0][am] = av.x;
        As[ak + 1][am] = av.y;
        As[ak + 2][am] = av.z;
        As[ak + 3][am] = av.w;
        float4 bv = *(const float4*)(B + (size_t)(k0 + bk) * NN + bn + bnn);
        *(float4*)&Bs[bk][bnn] = bv;
        __syncthreads();
#pragma unroll
        for (int kk = 0; kk < 8; kk++) {
            float ra[8], rb[8];
#pragma unroll
            for (int i = 0; i < 8; i++) ra[i] = As[kk][ty * 8 + i];
#pragma unroll
            for (int i = 0; i < 8; i++) rb[i] = Bs[kk][tx * 8 + i];
#pragma unroll
            for (int i = 0; i < 8; i++)
#pragma unroll
                for (int j = 0; j < 8; j++)
                    acc[i][j] = fmaf(ra[i], rb[j], acc[i][j]);
        }
        __syncthreads();
    }

#pragma unroll
    for (int i = 0; i < 8; i++) {
        int row = bm + ty * 8 + i;
        if (row < M) {
            float4 o0 = make_float4(acc[i][0], acc[i][1], acc[i][2], acc[i][3]);
            float4 o1 = make_float4(acc[i][4], acc[i][5], acc[i][6], acc[i][7]);
            *(float4*)(g_h + (size_t)row * NN + bn + tx * 8)     = o0;
            *(float4*)(g_h + (size_t)row * NN + bn + tx * 8 + 4) = o1;
        }
    }
}

// ---------------- attention dot products: als/ald ---------------------------
// one block per node, one warp per head
__global__ void k_attdot(const float* __restrict__ att_s,
                         const float* __restrict__ att_d)
{
    int n = blockIdx.x;
    int w = threadIdx.x >> 5, lane = threadIdx.x & 31;
    float2 hv = *(const float2*)(g_h + (size_t)n * FOUT + w * CC + lane * 2);
    float2 vs = *(const float2*)(att_s + w * CC + lane * 2);
    float2 vd = *(const float2*)(att_d + w * CC + lane * 2);
    float ps = hv.x * vs.x + hv.y * vs.y;
    float pd = hv.x * vd.x + hv.y * vd.y;
#pragma unroll
    for (int o = 16; o; o >>= 1) {
        ps += __shfl_xor_sync(0xffffffffu, ps, o);
        pd += __shfl_xor_sync(0xffffffffu, pd, o);
    }
    if (lane == 0) {
        g_als[n * HH + w] = ps;
        g_ald[n * HH + w] = pd;
    }
}

// ---------------- segment softmax: one warp per dst node --------------------
// stores unnormalized exp in g_alpha, reciprocal denom in g_rden
__global__ void k_softmax() {
    int node = blockIdx.x * 8 + (threadIdx.x >> 5);
    int lane = threadIdx.x & 31;
    if (node >= NNODE) return;
    int s0 = g_offs[node], s1 = g_offs[node + 1];

    float ad[8];
    {
        float4 a0 = *(const float4*)(g_ald + node * 8);
        float4 a1 = *(const float4*)(g_ald + node * 8 + 4);
        ad[0] = a0.x; ad[1] = a0.y; ad[2] = a0.z; ad[3] = a0.w;
        ad[4] = a1.x; ad[5] = a1.y; ad[6] = a1.z; ad[7] = a1.w;
    }

    float mx[8];
#pragma unroll
    for (int h = 0; h < 8; h++) mx[h] = -1e30f;

    for (int pos = s0 + lane; pos < s1; pos += 32) {
        int s = g_srcs[pos];
        float lw = g_lew[pos];
        float4 u = *(const float4*)(g_als + s * 8);
        float4 v = *(const float4*)(g_als + s * 8 + 4);
        float a[8] = {u.x, u.y, u.z, u.w, v.x, v.y, v.z, v.w};
#pragma unroll
        for (int h = 0; h < 8; h++) {
            float t = a[h] + ad[h];
            t = (t > 0.f) ? t : NEG * t;   // leaky_relu
            t += lw;
            a[h] = t;
            mx[h] = fmaxf(mx[h], t);
        }
        *(float4*)(g_alpha + (size_t)pos * 8)     = make_float4(a[0], a[1], a[2], a[3]);
        *(float4*)(g_alpha + (size_t)pos * 8 + 4) = make_float4(a[4], a[5], a[6], a[7]);
    }
#pragma unroll
    for (int o = 16; o; o >>= 1)
#pragma unroll
        for (int h = 0; h < 8; h++)
            mx[h] = fmaxf(mx[h], __shfl_xor_sync(0xffffffffu, mx[h], o));

    float sm[8];
#pragma unroll
    for (int h = 0; h < 8; h++) sm[h] = 0.f;

    for (int pos = s0 + lane; pos < s1; pos += 32) {
        float4 u = *(const float4*)(g_alpha + (size_t)pos * 8);
        float4 v = *(const float4*)(g_alpha + (size_t)pos * 8 + 4);
        float a[8] = {u.x, u.y, u.z, u.w, v.x, v.y, v.z, v.w};
#pragma unroll
        for (int h = 0; h < 8; h++) {
            float e = __expf(a[h] - mx[h]);
            a[h] = e;
            sm[h] += e;
        }
        *(float4*)(g_alpha + (size_t)pos * 8)     = make_float4(a[0], a[1], a[2], a[3]);
        *(float4*)(g_alpha + (size_t)pos * 8 + 4) = make_float4(a[4], a[5], a[6], a[7]);
    }
#pragma unroll
    for (int o = 16; o; o >>= 1)
#pragma unroll
        for (int h = 0; h < 8; h++)
            sm[h] += __shfl_xor_sync(0xffffffffu, sm[h], o);

    if (lane == 0) {
#pragma unroll
        for (int h = 0; h < 8; h++)
            g_rden[node * HH + h] = 1.f / sm[h];
    }
}

// ---------------- aggregation: one block per node, one warp per head --------
__global__ void k_aggregate(const float* __restrict__ bias,
                            float* __restrict__ out_ext, int do_relu)
{
    int n = blockIdx.x;
    int w = threadIdx.x >> 5, lane = threadIdx.x & 31;
    float* out = out_ext ? out_ext : g_x2;
    int s0 = g_offs[n], s1 = g_offs[n + 1];

    float accx = 0.f, accy = 0.f;
    for (int base = s0; base < s1; base += 32) {
        int idx = base + lane;
        int   mys = (idx < s1) ? g_srcs[idx] : 0;
        float myw = (idx < s1) ? g_alpha[(size_t)idx * 8 + w] : 0.f;
        int m = min(32, s1 - base);
        for (int j = 0; j < m; j++) {
            int   s  = __shfl_sync(0xffffffffu, mys, j);
            float wv = __shfl_sync(0xffffffffu, myw, j);
            float2 hv = *(const float2*)(g_h + (size_t)s * FOUT + w * CC + lane * 2);
            accx = fmaf(wv, hv.x, accx);
            accy = fmaf(wv, hv.y, accy);
        }
    }
    float r = g_rden[n * HH + w];
    float2 b = *(const float2*)(bias + w * CC + lane * 2);
    float ox = fmaf(accx, r, b.x);
    float oy = fmaf(accy, r, b.y);
    if (do_relu) { ox = fmaxf(ox, 0.f); oy = fmaxf(oy, 0.f); }
    *(float2*)(out + (size_t)n * FOUT + w * CC + lane * 2) = make_float2(ox, oy);
}

// ---------------- launch -----------------------------------------------------
extern "C" void kernel_launch(void* const* d_in, const int* in_sizes, int n_in,
                              void* d_out, int out_size)
{
    const float* x   = (const float*)d_in[0];
    const int*   ei  = (const int*)  d_in[1];
    const float* ew  = (const float*)d_in[2];
    const float* W1  = (const float*)d_in[3];
    const float* as1 = (const float*)d_in[4];
    const float* ad1 = (const float*)d_in[5];
    const float* b1  = (const float*)d_in[6];
    const float* W2  = (const float*)d_in[7];
    const float* as2 = (const float*)d_in[8];
    const float* ad2 = (const float*)d_in[9];
    const float* b2  = (const float*)d_in[10];
    float* out = (float*)d_out;

    // CSR build (shared by both layers)
    k_zero_cnt<<<(NNODE + 255) / 256, 256>>>();
    k_hist<<<(ETOT + 255) / 256, 256>>>(ei);
    k_scan<<<1, 1024>>>();
    k_scatter<<<(ETOT + 255) / 256, 256>>>(ei, ew);

    dim3 ggrid(FOUT / 128, (NNODE + 127) / 128);

    // layer 1
    k_sgemm<<<ggrid, 256>>>(x, W1, NNODE, FIN, 0);
    k_attdot<<<NNODE, 256>>>(as1, ad1);
    k_softmax<<<(NNODE + 7) / 8, 256>>>();
    k_aggregate<<<NNODE, 256>>>(b1, nullptr, 1);      // -> g_x2 with ReLU

    // layer 2
    k_sgemm<<<ggrid, 256>>>(nullptr, W2, NNODE, FOUT, 1);
    k_attdot<<<NNODE, 256>>>(as2, ad2);
    k_softmax<<<(NNODE + 7) / 8, 256>>>();
    k_aggregate<<<NNODE, 256>>>(b2, out, 0);          // -> d_out, no ReLU
}

// round 2
// speedup vs baseline: 1.1890x; 1.1890x over previous
#include <cuda_runtime.h>
#include <math.h>
#include <stdint.h>

#define NNODE 10000
#define NEDGE 320000
#define ETOT  (NEDGE + NNODE)
#define FIN   256
#define HH    8
#define CC    64
#define FOUT  512   /* HH*CC */
#define NEG   0.2f

// ---------------- static device scratch (no allocations allowed) ------------
__device__ float g_h[NNODE * FOUT];       // per-layer GEMM output  (20.5 MB)
__device__ float g_x2[NNODE * FOUT];      // layer-1 activated output (20.5 MB)
__device__ float g_als[NNODE * HH];
__device__ float g_ald[NNODE * HH];
__device__ float g_alpha[ETOT * HH];      // per-(edge,head) attn scratch (10.6 MB)
__device__ float g_rden[NNODE * HH];      // 1/softmax-denominator
__device__ int   g_cnt[NNODE];
__device__ int   g_offs[NNODE + 1];
__device__ int   g_cursor[NNODE];
__device__ int   g_srcs[ETOT];            // dst-sorted CSR: src per slot
__device__ float g_lew[ETOT];             // dst-sorted CSR: log2(edge_weight)

// ---------------- CSR build -------------------------------------------------
__global__ void k_zero_cnt() {
    int i = blockIdx.x * blockDim.x + threadIdx.x;
    if (i < NNODE) g_cnt[i] = 0;
}

__global__ void k_hist(const int* __restrict__ ei) {
    int e = blockIdx.x * blockDim.x + threadIdx.x;
    if (e >= ETOT) return;
    int d = (e < NEDGE) ? ei[NEDGE + e] : (e - NEDGE);
    atomicAdd(&g_cnt[d], 1);
}

__global__ void k_scan() {
    __shared__ int sh[1024];
    int t = threadIdx.x;
    const int CH = (NNODE + 1023) / 1024;   // 10
    int base = t * CH;
    int s = 0;
    for (int i = 0; i < CH; i++) {
        int idx = base + i;
        if (idx < NNODE) s += g_cnt[idx];
    }
    sh[t] = s;
    __syncthreads();
    for (int off = 1; off < 1024; off <<= 1) {
        int v = (t >= off) ? sh[t - off] : 0;
        __syncthreads();
        sh[t] += v;
        __syncthreads();
    }
    int run = (t == 0) ? 0 : sh[t - 1];
    for (int i = 0; i < CH; i++) {
        int idx = base + i;
        if (idx < NNODE) {
            g_offs[idx]   = run;
            g_cursor[idx] = run;
            run += g_cnt[idx];
        }
    }
    if (t == 1023) g_offs[NNODE] = run;
}

__global__ void k_scatter(const int* __restrict__ ei, const float* __restrict__ ew) {
    int e = blockIdx.x * blockDim.x + threadIdx.x;
    if (e >= ETOT) return;
    int s, d; float lw;
    if (e < NEDGE) {
        s = ei[e]; d = ei[NEDGE + e];
        lw = log2f(ew[e]);
    } else {
        s = d = e - NEDGE;
        lw = 0.f;
    }
    int pos = atomicAdd(&g_cursor[d], 1);
    g_srcs[pos] = s;
    g_lew[pos]  = lw;
}

// ---------------- 3xTF32 tensor-core GEMM: g_h[M,512] = A[M,K] @ B[K,512] ---
// 128x128 block tile, BK=8, 256 threads (8 warps), warp tile 64x32 via
// mma.sync.m16n8k8.tf32. A is split hi/lo at smem-store time; products
// hi*hi + hi*lo + lo*hi recover ~fp32 accuracy (missing lo*lo ~ 2^-22 rel).
__device__ __forceinline__ uint32_t f2tf32(float x) {
    uint32_t r;
    asm("cvt.rna.tf32.f32 %0, %1;" : "=r"(r) : "f"(x));
    return r;
}

__device__ __forceinline__ void mma_tf32(float c[4],
                                         uint32_t a0, uint32_t a1, uint32_t a2, uint32_t a3,
                                         uint32_t b0, uint32_t b1) {
    asm volatile(
        "mma.sync.aligned.m16n8k8.row.col.f32.tf32.tf32.f32 "
        "{%0,%1,%2,%3}, {%4,%5,%6,%7}, {%8,%9}, {%0,%1,%2,%3};"
        : "+f"(c[0]), "+f"(c[1]), "+f"(c[2]), "+f"(c[3])
        : "r"(a0), "r"(a1), "r"(a2), "r"(a3), "r"(b0), "r"(b1));
}

#define SPITCH 136   /* words; 136 mod 32 = 8 -> conflict-free frag LDS */

__global__ __launch_bounds__(256) void k_gemm_tc(
    const float* __restrict__ A_ext, const float* __restrict__ B,
    int M, int K, int a_internal)
{
    __shared__ uint32_t AsH[8][SPITCH];
    __shared__ uint32_t AsL[8][SPITCH];
    __shared__ uint32_t BsH[8][SPITCH];
    __shared__ uint32_t BsL[8][SPITCH];

    const float* A = a_internal ? g_x2 : A_ext;
    const int NN = FOUT;

    int bm = blockIdx.y * 128;
    int bn = blockIdx.x * 128;
    int tid  = threadIdx.x;
    int lane = tid & 31;
    int warp = tid >> 5;
    int wm = (warp & 1) * 64;   // warp row offset in block tile
    int wn = (warp >> 1) * 32;  // warp col offset in block tile

    // gmem->smem thread mapping
    int am = tid >> 1;             // A row within tile (0..127)
    int ak = (tid & 1) * 4;        // A k offset (0 or 4)
    int bk = tid >> 5;             // B k row (0..7)
    int bnn = (tid & 31) * 4;      // B col offset (0..124)

    float acc[4][4][4];
#pragma unroll
    for (int mi = 0; mi < 4; mi++)
#pragma unroll
        for (int ni = 0; ni < 4; ni++)
#pragma unroll
            for (int r = 0; r < 4; r++) acc[mi][ni][r] = 0.f;

    for (int k0 = 0; k0 < K; k0 += 8) {
        // ---- load A tile (128x8), split into tf32 hi/lo ----
        {
            int row = bm + am;
            float4 av = (row < M)
                ? *(const float4*)(A + (size_t)row * K + k0 + ak)
                : make_float4(0.f, 0.f, 0.f, 0.f);
            float v[4] = {av.x, av.y, av.z, av.w};
#pragma unroll
            for (int j = 0; j < 4; j++) {
                uint32_t hb = f2tf32(v[j]);
                float hf = __uint_as_float(hb);
                uint32_t lb = f2tf32(v[j] - hf);
                AsH[ak + j][am] = hb;
                AsL[ak + j][am] = lb;
            }
        }
        // ---- load B tile (8x128), split into tf32 hi/lo ----
        {
            float4 bv = *(const float4*)(B + (size_t)(k0 + bk) * NN + bn + bnn);
            float v[4] = {bv.x, bv.y, bv.z, bv.w};
            uint32_t hb[4], lb[4];
#pragma unroll
            for (int j = 0; j < 4; j++) {
                hb[j] = f2tf32(v[j]);
                lb[j] = f2tf32(v[j] - __uint_as_float(hb[j]));
            }
            *(uint4*)&BsH[bk][bnn] = make_uint4(hb[0], hb[1], hb[2], hb[3]);
            *(uint4*)&BsL[bk][bnn] = make_uint4(lb[0], lb[1], lb[2], lb[3]);
        }
        __syncthreads();

        // ---- fragment loads ----
        int fk = lane & 3;
        int fg = lane >> 2;
        uint32_t ah[4][4], al[4][4];
#pragma unroll
        for (int mi = 0; mi < 4; mi++) {
            int m0 = wm + mi * 16 + fg;
            ah[mi][0] = AsH[fk][m0];      ah[mi][1] = AsH[fk][m0 + 8];
            ah[mi][2] = AsH[fk + 4][m0];  ah[mi][3] = AsH[fk + 4][m0 + 8];
            al[mi][0] = AsL[fk][m0];      al[mi][1] = AsL[fk][m0 + 8];
            al[mi][2] = AsL[fk + 4][m0];  al[mi][3] = AsL[fk + 4][m0 + 8];
        }
        uint32_t bh[4][2], bl[4][2];
#pragma unroll
        for (int ni = 0; ni < 4; ni++) {
            int n0 = wn + ni * 8 + fg;
            bh[ni][0] = BsH[fk][n0];      bh[ni][1] = BsH[fk + 4][n0];
            bl[ni][0] = BsL[fk][n0];      bl[ni][1] = BsL[fk + 4][n0];
        }

        // ---- 3xTF32 mma ----
#pragma unroll
        for (int mi = 0; mi < 4; mi++)
#pragma unroll
            for (int ni = 0; ni < 4; ni++) {
                mma_tf32(acc[mi][ni], ah[mi][0], ah[mi][1], ah[mi][2], ah[mi][3],
                         bh[ni][0], bh[ni][1]);
                mma_tf32(acc[mi][ni], ah[mi][0], ah[mi][1], ah[mi][2], ah[mi][3],
                         bl[ni][0], bl[ni][1]);
                mma_tf32(acc[mi][ni], al[mi][0], al[mi][1], al[mi][2], al[mi][3],
                         bh[ni][0], bh[ni][1]);
            }
        __syncthreads();
    }

    // ---- epilogue: write g_h ----
    int fg = lane >> 2;
    int fk = lane & 3;
#pragma unroll
    for (int mi = 0; mi < 4; mi++) {
        int r0 = bm + wm + mi * 16 + fg;
        int r1 = r0 + 8;
#pragma unroll
        for (int ni = 0; ni < 4; ni++) {
            int col = bn + wn + ni * 8 + fk * 2;
            if (r0 < M)
                *(float2*)(g_h + (size_t)r0 * NN + col) =
                    make_float2(acc[mi][ni][0], acc[mi][ni][1]);
            if (r1 < M)
                *(float2*)(g_h + (size_t)r1 * NN + col) =
                    make_float2(acc[mi][ni][2], acc[mi][ni][3]);
        }
    }
}

// ---------------- attention dot products: als/ald ---------------------------
// one block per node, one warp per head
__global__ void k_attdot(const float* __restrict__ att_s,
                         const float* __restrict__ att_d)
{
    int n = blockIdx.x;
    int w = threadIdx.x >> 5, lane = threadIdx.x & 31;
    float2 hv = *(const float2*)(g_h + (size_t)n * FOUT + w * CC + lane * 2);
    float2 vs = *(const float2*)(att_s + w * CC + lane * 2);
    float2 vd = *(const float2*)(att_d + w * CC + lane * 2);
    float ps = hv.x * vs.x + hv.y * vs.y;
    float pd = hv.x * vd.x + hv.y * vd.y;
#pragma unroll
    for (int o = 16; o; o >>= 1) {
        ps += __shfl_xor_sync(0xffffffffu, ps, o);
        pd += __shfl_xor_sync(0xffffffffu, pd, o);
    }
    if (lane == 0) {
        g_als[n * HH + w] = ps;
        g_ald[n * HH + w] = pd;
    }
}

// ---------------- segment softmax: one warp per dst node --------------------
// stores unnormalized exp in g_alpha, reciprocal denom in g_rden
__global__ void k_softmax() {
    int node = blockIdx.x * 8 + (threadIdx.x >> 5);
    int lane = threadIdx.x & 31;
    if (node >= NNODE) return;
    int s0 = g_offs[node], s1 = g_offs[node + 1];

    float ad[8];
    {
        float4 a0 = *(const float4*)(g_ald + node * 8);
        float4 a1 = *(const float4*)(g_ald + node * 8 + 4);
        ad[0] = a0.x; ad[1] = a0.y; ad[2] = a0.z; ad[3] = a0.w;
        ad[4] = a1.x; ad[5] = a1.y; ad[6] = a1.z; ad[7] = a1.w;
    }

    float mx[8];
#pragma unroll
    for (int h = 0; h < 8; h++) mx[h] = -1e30f;

    for (int pos = s0 + lane; pos < s1; pos += 32) {
        int s = g_srcs[pos];
        float lw = g_lew[pos];
        float4 u = *(const float4*)(g_als + s * 8);
        float4 v = *(const float4*)(g_als + s * 8 + 4);
        float a[8] = {u.x, u.y, u.z, u.w, v.x, v.y, v.z, v.w};
#pragma unroll
        for (int h = 0; h < 8; h++) {
            float t = a[h] + ad[h];
            t = (t > 0.f) ? t : NEG * t;   // leaky_relu
            t += lw;
            a[h] = t;
            mx[h] = fmaxf(mx[h], t);
        }
        *(float4*)(g_alpha + (size_t)pos * 8)     = make_float4(a[0], a[1], a[2], a[3]);
        *(float4*)(g_alpha + (size_t)pos * 8 + 4) = make_float4(a[4], a[5], a[6], a[7]);
    }
#pragma unroll
    for (int o = 16; o; o >>= 1)
#pragma unroll
        for (int h = 0; h < 8; h++)
            mx[h] = fmaxf(mx[h], __shfl_xor_sync(0xffffffffu, mx[h], o));

    float sm[8];
#pragma unroll
    for (int h = 0; h < 8; h++) sm[h] = 0.f;

    for (int pos = s0 + lane; pos < s1; pos += 32) {
        float4 u = *(const float4*)(g_alpha + (size_t)pos * 8);
        float4 v = *(const float4*)(g_alpha + (size_t)pos * 8 + 4);
        float a[8] = {u.x, u.y, u.z, u.w, v.x, v.y, v.z, v.w};
#pragma unroll
        for (int h = 0; h < 8; h++) {
            float e = __expf(a[h] - mx[h]);
            a[h] = e;
            sm[h] += e;
        }
        *(float4*)(g_alpha + (size_t)pos * 8)     = make_float4(a[0], a[1], a[2], a[3]);
        *(float4*)(g_alpha + (size_t)pos * 8 + 4) = make_float4(a[4], a[5], a[6], a[7]);
    }
#pragma unroll
    for (int o = 16; o; o >>= 1)
#pragma unroll
        for (int h = 0; h < 8; h++)
            sm[h] += __shfl_xor_sync(0xffffffffu, sm[h], o);

    if (lane == 0) {
#pragma unroll
        for (int h = 0; h < 8; h++)
            g_rden[node * HH + h] = 1.f / sm[h];
    }
}

// ---------------- aggregation: one block per node, one warp per head --------
__global__ void k_aggregate(const float* __restrict__ bias,
                            float* __restrict__ out_ext, int do_relu)
{
    int n = blockIdx.x;
    int w = threadIdx.x >> 5, lane = threadIdx.x & 31;
    float* out = out_ext ? out_ext : g_x2;
    int s0 = g_offs[n], s1 = g_offs[n + 1];

    float accx = 0.f, accy = 0.f;
    for (int base = s0; base < s1; base += 32) {
        int idx = base + lane;
        int   mys = (idx < s1) ? g_srcs[idx] : 0;
        float myw = (idx < s1) ? g_alpha[(size_t)idx * 8 + w] : 0.f;
        int m = min(32, s1 - base);
        for (int j = 0; j < m; j++) {
            int   s  = __shfl_sync(0xffffffffu, mys, j);
            float wv = __shfl_sync(0xffffffffu, myw, j);
            float2 hv = *(const float2*)(g_h + (size_t)s * FOUT + w * CC + lane * 2);
            accx = fmaf(wv, hv.x, accx);
            accy = fmaf(wv, hv.y, accy);
        }
    }
    float r = g_rden[n * HH + w];
    float2 b = *(const float2*)(bias + w * CC + lane * 2);
    float ox = fmaf(accx, r, b.x);
    float oy = fmaf(accy, r, b.y);
    if (do_relu) { ox = fmaxf(ox, 0.f); oy = fmaxf(oy, 0.f); }
    *(float2*)(out + (size_t)n * FOUT + w * CC + lane * 2) = make_float2(ox, oy);
}

// ---------------- launch -----------------------------------------------------
extern "C" void kernel_launch(void* const* d_in, const int* in_sizes, int n_in,
                              void* d_out, int out_size)
{
    const float* x   = (const float*)d_in[0];
    const int*   ei  = (const int*)  d_in[1];
    const float* ew  = (const float*)d_in[2];
    const float* W1  = (const float*)d_in[3];
    const float* as1 = (const float*)d_in[4];
    const float* ad1 = (const float*)d_in[5];
    const float* b1  = (const float*)d_in[6];
    const float* W2  = (const float*)d_in[7];
    const float* as2 = (const float*)d_in[8];
    const float* ad2 = (const float*)d_in[9];
    const float* b2  = (const float*)d_in[10];
    float* out = (float*)d_out;

    // CSR build (shared by both layers)
    k_zero_cnt<<<(NNODE + 255) / 256, 256>>>();
    k_hist<<<(ETOT + 255) / 256, 256>>>(ei);
    k_scan<<<1, 1024>>>();
    k_scatter<<<(ETOT + 255) / 256, 256>>>(ei, ew);

    dim3 ggrid(FOUT / 128, (NNODE + 127) / 128);

    // layer 1
    k_gemm_tc<<<ggrid, 256>>>(x, W1, NNODE, FIN, 0);
    k_attdot<<<NNODE, 256>>>(as1, ad1);
    k_softmax<<<(NNODE + 7) / 8, 256>>>();
    k_aggregate<<<NNODE, 256>>>(b1, nullptr, 1);      // -> g_x2 with ReLU

    // layer 2
    k_gemm_tc<<<ggrid, 256>>>(nullptr, W2, NNODE, FOUT, 1);
    k_attdot<<<NNODE, 256>>>(as2, ad2);
    k_softmax<<<(NNODE + 7) / 8, 256>>>();
    k_aggregate<<<NNODE, 256>>>(b2, out, 0);          // -> d_out, no ReLU
}

// round 3
// speedup vs baseline: 1.3396x; 1.1267x over previous
#include <cuda_runtime.h>
#include <cuda_fp16.h>
#include <math.h>
#include <stdint.h>

#define NNODE 10000
#define NEDGE 320000
#define ETOT  (NEDGE + NNODE)
#define FIN   256
#define HH    8
#define CC    64
#define FOUT  512   /* HH*CC */
#define NEG   0.2f

// ---------------- static device scratch (no allocations allowed) ------------
__device__ __half g_hh[NNODE * FOUT];     // GEMM output, fp16 mirror (10.2 MB)
__device__ float g_x2[NNODE * FOUT];      // layer-1 activated output (20.5 MB)
__device__ float g_als[NNODE * HH];       // atomic-accumulated att dots
__device__ float g_ald[NNODE * HH];
__device__ float g_alpha[ETOT * HH];      // per-(edge,head) attn scratch (10.6 MB)
__device__ float g_rden[NNODE * HH];      // 1/softmax-denominator
__device__ int   g_cnt[NNODE];
__device__ int   g_offs[NNODE + 1];
__device__ int   g_cursor[NNODE];
__device__ int   g_srcs[ETOT];            // dst-sorted CSR: src per slot
__device__ float g_lew[ETOT];             // dst-sorted CSR: log2(edge_weight)

// ---------------- zero init (cnt + att dot accumulators) --------------------
__global__ void k_zero() {
    int i = blockIdx.x * blockDim.x + threadIdx.x;
    if (i < NNODE * HH) { g_als[i] = 0.f; g_ald[i] = 0.f; }
    if (i < NNODE) g_cnt[i] = 0;
}

__global__ void k_hist(const int* __restrict__ ei) {
    int e = blockIdx.x * blockDim.x + threadIdx.x;
    if (e >= ETOT) return;
    int d = (e < NEDGE) ? ei[NEDGE + e] : (e - NEDGE);
    atomicAdd(&g_cnt[d], 1);
}

__global__ void k_scan() {
    __shared__ int sh[1024];
    int t = threadIdx.x;
    const int CH = (NNODE + 1023) / 1024;   // 10
    int base = t * CH;
    int s = 0;
    for (int i = 0; i < CH; i++) {
        int idx = base + i;
        if (idx < NNODE) s += g_cnt[idx];
    }
    sh[t] = s;
    __syncthreads();
    for (int off = 1; off < 1024; off <<= 1) {
        int v = (t >= off) ? sh[t - off] : 0;
        __syncthreads();
        sh[t] += v;
        __syncthreads();
    }
    int run = (t == 0) ? 0 : sh[t - 1];
    for (int i = 0; i < CH; i++) {
        int idx = base + i;
        if (idx < NNODE) {
            g_offs[idx]   = run;
            g_cursor[idx] = run;
            run += g_cnt[idx];
        }
    }
    if (t == 1023) g_offs[NNODE] = run;
}

__global__ void k_scatter(const int* __restrict__ ei, const float* __restrict__ ew) {
    int e = blockIdx.x * blockDim.x + threadIdx.x;
    if (e >= ETOT) return;
    int s, d; float lw;
    if (e < NEDGE) {
        s = ei[e]; d = ei[NEDGE + e];
        lw = log2f(ew[e]);
    } else {
        s = d = e - NEDGE;
        lw = 0.f;
    }
    int pos = atomicAdd(&g_cursor[d], 1);
    g_srcs[pos] = s;
    g_lew[pos]  = lw;
}

// ---------------- 3xTF32 tensor-core GEMM + fused att-dot epilogue ----------
// C = A[M,K] @ B[K,512]; h stored fp16 into g_hh; als/ald accumulated via
// atomicAdd from fp32 accumulators. Double-buffered smem, LDG prefetch.
__device__ __forceinline__ uint32_t f2tf32(float x) {
    uint32_t r;
    asm("cvt.rna.tf32.f32 %0, %1;" : "=r"(r) : "f"(x));
    return r;
}

__device__ __forceinline__ void mma_tf32(float c[4],
                                         uint32_t a0, uint32_t a1, uint32_t a2, uint32_t a3,
                                         uint32_t b0, uint32_t b1) {
    asm volatile(
        "mma.sync.aligned.m16n8k8.row.col.f32.tf32.tf32.f32 "
        "{%0,%1,%2,%3}, {%4,%5,%6,%7}, {%8,%9}, {%0,%1,%2,%3};"
        : "+f"(c[0]), "+f"(c[1]), "+f"(c[2]), "+f"(c[3])
        : "r"(a0), "r"(a1), "r"(a2), "r"(a3), "r"(b0), "r"(b1));
}

#define SPITCH 136   /* words; 136 mod 32 = 8 -> conflict-free frag LDS */

__global__ __launch_bounds__(256) void k_gemm_tc(
    const float* __restrict__ A_ext, const float* __restrict__ B,
    const float* __restrict__ att_s, const float* __restrict__ att_d,
    int M, int K, int a_internal)
{
    __shared__ uint32_t AsH[2][8][SPITCH];
    __shared__ uint32_t AsL[2][8][SPITCH];
    __shared__ uint32_t BsH[2][8][SPITCH];
    __shared__ uint32_t BsL[2][8][SPITCH];

    const float* A = a_internal ? g_x2 : A_ext;
    const int NN = FOUT;

    int bm = blockIdx.y * 128;
    int bn = blockIdx.x * 128;
    int tid  = threadIdx.x;
    int lane = tid & 31;
    int warp = tid >> 5;
    int wm = (warp & 1) * 64;   // warp row offset in block tile
    int wn = (warp >> 1) * 32;  // warp col offset in block tile

    // gmem->smem thread mapping
    int am = tid >> 1;             // A row within tile (0..127)
    int ak = (tid & 1) * 4;        // A k offset (0 or 4)
    int bk = tid >> 5;             // B k row (0..7)
    int bnn = (tid & 31) * 4;      // B col offset (0..124)
    int arow = bm + am;

    float acc[4][4][4];
#pragma unroll
    for (int mi = 0; mi < 4; mi++)
#pragma unroll
        for (int ni = 0; ni < 4; ni++)
#pragma unroll
            for (int r = 0; r < 4; r++) acc[mi][ni][r] = 0.f;

    // prologue: load tile 0 and store to buf 0
    float4 av = (arow < M) ? *(const float4*)(A + (size_t)arow * K + ak)
                           : make_float4(0.f, 0.f, 0.f, 0.f);
    float4 bv = *(const float4*)(B + (size_t)bk * NN + bn + bnn);
    {
        float va[4] = {av.x, av.y, av.z, av.w};
        float vb[4] = {bv.x, bv.y, bv.z, bv.w};
        uint32_t hbb[4], lbb[4];
#pragma unroll
        for (int j = 0; j < 4; j++) {
            uint32_t hb = f2tf32(va[j]);
            AsH[0][ak + j][am] = hb;
            AsL[0][ak + j][am] = f2tf32(va[j] - __uint_as_float(hb));
            hbb[j] = f2tf32(vb[j]);
            lbb[j] = f2tf32(vb[j] - __uint_as_float(hbb[j]));
        }
        *(uint4*)&BsH[0][bk][bnn] = make_uint4(hbb[0], hbb[1], hbb[2], hbb[3]);
        *(uint4*)&BsL[0][bk][bnn] = make_uint4(lbb[0], lbb[1], lbb[2], lbb[3]);
    }
    __syncthreads();

    int buf = 0;
    for (int k0 = 0; k0 < K; k0 += 8) {
        // prefetch next tile (gmem -> regs), overlapped with mma below
        bool has_next = (k0 + 8) < K;
        if (has_next) {
            av = (arow < M) ? *(const float4*)(A + (size_t)arow * K + k0 + 8 + ak)
                            : make_float4(0.f, 0.f, 0.f, 0.f);
            bv = *(const float4*)(B + (size_t)(k0 + 8 + bk) * NN + bn + bnn);
        }

        // ---- fragment loads from current buffer ----
        int fk = lane & 3;
        int fg = lane >> 2;
        uint32_t ah[4][4], al[4][4];
#pragma unroll
        for (int mi = 0; mi < 4; mi++) {
            int m0 = wm + mi * 16 + fg;
            ah[mi][0] = AsH[buf][fk][m0];      ah[mi][1] = AsH[buf][fk][m0 + 8];
            ah[mi][2] = AsH[buf][fk + 4][m0];  ah[mi][3] = AsH[buf][fk + 4][m0 + 8];
            al[mi][0] = AsL[buf][fk][m0];      al[mi][1] = AsL[buf][fk][m0 + 8];
            al[mi][2] = AsL[buf][fk + 4][m0];  al[mi][3] = AsL[buf][fk + 4][m0 + 8];
        }
        uint32_t bh[4][2], bl[4][2];
#pragma unroll
        for (int ni = 0; ni < 4; ni++) {
            int n0 = wn + ni * 8 + fg;
            bh[ni][0] = BsH[buf][fk][n0];      bh[ni][1] = BsH[buf][fk + 4][n0];
            bl[ni][0] = BsL[buf][fk][n0];      bl[ni][1] = BsL[buf][fk + 4][n0];
        }

        // ---- 3xTF32 mma ----
#pragma unroll
        for (int mi = 0; mi < 4; mi++)
#pragma unroll
            for (int ni = 0; ni < 4; ni++) {
                mma_tf32(acc[mi][ni], ah[mi][0], ah[mi][1], ah[mi][2], ah[mi][3],
                         bh[ni][0], bh[ni][1]);
                mma_tf32(acc[mi][ni], ah[mi][0], ah[mi][1], ah[mi][2], ah[mi][3],
                         bl[ni][0], bl[ni][1]);
                mma_tf32(acc[mi][ni], al[mi][0], al[mi][1], al[mi][2], al[mi][3],
                         bh[ni][0], bh[ni][1]);
            }

        // ---- store next tile into other buffer ----
        if (has_next) {
            int nb = buf ^ 1;
            float va[4] = {av.x, av.y, av.z, av.w};
            float vb2[4] = {bv.x, bv.y, bv.z, bv.w};
            uint32_t hbb[4], lbb[4];
#pragma unroll
            for (int j = 0; j < 4; j++) {
                uint32_t hb = f2tf32(va[j]);
                AsH[nb][ak + j][am] = hb;
                AsL[nb][ak + j][am] = f2tf32(va[j] - __uint_as_float(hb));
                hbb[j] = f2tf32(vb2[j]);
                lbb[j] = f2tf32(vb2[j] - __uint_as_float(hbb[j]));
            }
            *(uint4*)&BsH[nb][bk][bnn] = make_uint4(hbb[0], hbb[1], hbb[2], hbb[3]);
            *(uint4*)&BsL[nb][bk][bnn] = make_uint4(lbb[0], lbb[1], lbb[2], lbb[3]);
        }
        __syncthreads();
        buf ^= 1;
    }

    // ---- epilogue: fp16 store + fused att dot products ----
    int fg = lane >> 2;
    int fk = lane & 3;
    int headg = (bn + wn) >> 6;   // warp's 32 cols lie in exactly one head

    float vsv[4][2], vdv[4][2];
#pragma unroll
    for (int ni = 0; ni < 4; ni++) {
        int c = bn + wn + ni * 8 + fk * 2;
        vsv[ni][0] = att_s[c]; vsv[ni][1] = att_s[c + 1];
        vdv[ni][0] = att_d[c]; vdv[ni][1] = att_d[c + 1];
    }

#pragma unroll
    for (int mi = 0; mi < 4; mi++) {
        int r0 = bm + wm + mi * 16 + fg;
        int r1 = r0 + 8;
        float s0 = 0.f, d0 = 0.f, s1 = 0.f, d1 = 0.f;
#pragma unroll
        for (int ni = 0; ni < 4; ni++) {
            int col = bn + wn + ni * 8 + fk * 2;
            __half2 h01 = __floats2half2_rn(acc[mi][ni][0], acc[mi][ni][1]);
            __half2 h23 = __floats2half2_rn(acc[mi][ni][2], acc[mi][ni][3]);
            if (r0 < M) *(__half2*)(g_hh + (size_t)r0 * NN + col) = h01;
            if (r1 < M) *(__half2*)(g_hh + (size_t)r1 * NN + col) = h23;
            s0 += acc[mi][ni][0] * vsv[ni][0] + acc[mi][ni][1] * vsv[ni][1];
            d0 += acc[mi][ni][0] * vdv[ni][0] + acc[mi][ni][1] * vdv[ni][1];
            s1 += acc[mi][ni][2] * vsv[ni][0] + acc[mi][ni][3] * vsv[ni][1];
            d1 += acc[mi][ni][2] * vdv[ni][0] + acc[mi][ni][3] * vdv[ni][1];
        }
        // reduce over fk (lanes differing in bits 0..1)
#pragma unroll
        for (int off = 2; off; off >>= 1) {
            s0 += __shfl_xor_sync(0xffffffffu, s0, off);
            d0 += __shfl_xor_sync(0xffffffffu, d0, off);
            s1 += __shfl_xor_sync(0xffffffffu, s1, off);
            d1 += __shfl_xor_sync(0xffffffffu, d1, off);
        }
        if (fk == 0) {
            if (r0 < M) {
                atomicAdd(&g_als[r0 * HH + headg], s0);
                atomicAdd(&g_ald[r0 * HH + headg], d0);
            }
            if (r1 < M) {
                atomicAdd(&g_als[r1 * HH + headg], s1);
                atomicAdd(&g_ald[r1 * HH + headg], d1);
            }
        }
    }
}

// ---------------- segment softmax: one warp per dst node --------------------
__global__ void k_softmax() {
    int node = blockIdx.x * 8 + (threadIdx.x >> 5);
    int lane = threadIdx.x & 31;
    if (node >= NNODE) return;
    int s0 = g_offs[node], s1 = g_offs[node + 1];

    float ad[8];
    {
        float4 a0 = *(const float4*)(g_ald + node * 8);
        float4 a1 = *(const float4*)(g_ald + node * 8 + 4);
        ad[0] = a0.x; ad[1] = a0.y; ad[2] = a0.z; ad[3] = a0.w;
        ad[4] = a1.x; ad[5] = a1.y; ad[6] = a1.z; ad[7] = a1.w;
    }

    float mx[8];
#pragma unroll
    for (int h = 0; h < 8; h++) mx[h] = -1e30f;

    for (int pos = s0 + lane; pos < s1; pos += 32) {
        int s = g_srcs[pos];
        float lw = g_lew[pos];
        float4 u = *(const float4*)(g_als + s * 8);
        float4 v = *(const float4*)(g_als + s * 8 + 4);
        float a[8] = {u.x, u.y, u.z, u.w, v.x, v.y, v.z, v.w};
#pragma unroll
        for (int h = 0; h < 8; h++) {
            float t = a[h] + ad[h];
            t = (t > 0.f) ? t : NEG * t;   // leaky_relu
            t += lw;
            a[h] = t;
            mx[h] = fmaxf(mx[h], t);
        }
        *(float4*)(g_alpha + (size_t)pos * 8)     = make_float4(a[0], a[1], a[2], a[3]);
        *(float4*)(g_alpha + (size_t)pos * 8 + 4) = make_float4(a[4], a[5], a[6], a[7]);
    }
#pragma unroll
    for (int o = 16; o; o >>= 1)
#pragma unroll
        for (int h = 0; h < 8; h++)
            mx[h] = fmaxf(mx[h], __shfl_xor_sync(0xffffffffu, mx[h], o));

    float sm[8];
#pragma unroll
    for (int h = 0; h < 8; h++) sm[h] = 0.f;

    for (int pos = s0 + lane; pos < s1; pos += 32) {
        float4 u = *(const float4*)(g_alpha + (size_t)pos * 8);
        float4 v = *(const float4*)(g_alpha + (size_t)pos * 8 + 4);
        float a[8] = {u.x, u.y, u.z, u.w, v.x, v.y, v.z, v.w};
#pragma unroll
        for (int h = 0; h < 8; h++) {
            float e = __expf(a[h] - mx[h]);
            a[h] = e;
            sm[h] += e;
        }
        *(float4*)(g_alpha + (size_t)pos * 8)     = make_float4(a[0], a[1], a[2], a[3]);
        *(float4*)(g_alpha + (size_t)pos * 8 + 4) = make_float4(a[4], a[5], a[6], a[7]);
    }
#pragma unroll
    for (int o = 16; o; o >>= 1)
#pragma unroll
        for (int h = 0; h < 8; h++)
            sm[h] += __shfl_xor_sync(0xffffffffu, sm[h], o);

    if (lane == 0) {
#pragma unroll
        for (int h = 0; h < 8; h++)
            g_rden[node * HH + h] = 1.f / sm[h];
    }
}

// ---------------- aggregation: one block per node, one warp per head --------
// gathers fp16 h rows; also zeroes g_als/g_ald for the next layer's atomics.
__global__ void k_aggregate(const float* __restrict__ bias,
                            float* __restrict__ out_ext, int do_relu)
{
    int n = blockIdx.x;
    int w = threadIdx.x >> 5, lane = threadIdx.x & 31;
    float* out = out_ext ? out_ext : g_x2;
    int s0 = g_offs[n], s1 = g_offs[n + 1];

    float accx = 0.f, accy = 0.f;
    for (int base = s0; base < s1; base += 32) {
        int idx = base + lane;
        int   mys = (idx < s1) ? g_srcs[idx] : 0;
        float myw = (idx < s1) ? g_alpha[(size_t)idx * 8 + w] : 0.f;
        int m = min(32, s1 - base);
        for (int j = 0; j < m; j++) {
            int   s  = __shfl_sync(0xffffffffu, mys, j);
            float wv = __shfl_sync(0xffffffffu, myw, j);
            float2 hv = __half22float2(
                *(const __half2*)(g_hh + (size_t)s * FOUT + w * CC + lane * 2));
            accx = fmaf(wv, hv.x, accx);
            accy = fmaf(wv, hv.y, accy);
        }
    }
    float r = g_rden[n * HH + w];
    float2 b = *(const float2*)(bias + w * CC + lane * 2);
    float ox = fmaf(accx, r, b.x);
    float oy = fmaf(accy, r, b.y);
    if (do_relu) { ox = fmaxf(ox, 0.f); oy = fmaxf(oy, 0.f); }
    *(float2*)(out + (size_t)n * FOUT + w * CC + lane * 2) = make_float2(ox, oy);

    // zero att accumulators for the next layer's fused epilogue atomics
    if (lane == 0) {
        g_als[n * HH + w] = 0.f;
        g_ald[n * HH + w] = 0.f;
    }
}

// ---------------- launch -----------------------------------------------------
extern "C" void kernel_launch(void* const* d_in, const int* in_sizes, int n_in,
                              void* d_out, int out_size)
{
    const float* x   = (const float*)d_in[0];
    const int*   ei  = (const int*)  d_in[1];
    const float* ew  = (const float*)d_in[2];
    const float* W1  = (const float*)d_in[3];
    const float* as1 = (const float*)d_in[4];
    const float* ad1 = (const float*)d_in[5];
    const float* b1  = (const float*)d_in[6];
    const float* W2  = (const float*)d_in[7];
    const float* as2 = (const float*)d_in[8];
    const float* ad2 = (const float*)d_in[9];
    const float* b2  = (const float*)d_in[10];
    float* out = (float*)d_out;

    // CSR build + zero (shared by both layers)
    k_zero<<<(NNODE * HH + 255) / 256, 256>>>();
    k_hist<<<(ETOT + 255) / 256, 256>>>(ei);
    k_scan<<<1, 1024>>>();
    k_scatter<<<(ETOT + 255) / 256, 256>>>(ei, ew);

    dim3 ggrid(FOUT / 128, (NNODE + 127) / 128);

    // layer 1
    k_gemm_tc<<<ggrid, 256>>>(x, W1, as1, ad1, NNODE, FIN, 0);
    k_softmax<<<(NNODE + 7) / 8, 256>>>();
    k_aggregate<<<NNODE, 256>>>(b1, nullptr, 1);      // -> g_x2 with ReLU

    // layer 2
    k_gemm_tc<<<ggrid, 256>>>(nullptr, W2, as2, ad2, NNODE, FOUT, 1);
    k_softmax<<<(NNODE + 7) / 8, 256>>>();
    k_aggregate<<<NNODE, 256>>>(b2, out, 0);          // -> d_out, no ReLU
}

// round 5
// speedup vs baseline: 1.8319x; 1.3674x over previous
#include <cuda_runtime.h>
#include <cuda_fp16.h>
#include <cuda_bf16.h>
#include <math.h>
#include <stdint.h>

#define NNODE 10000
#define NEDGE 320000
#define ETOT  (NEDGE + NNODE)
#define FIN   256
#define HH    8
#define CC    64
#define FOUT  512   /* HH*CC */
#define NEG   0.2f

// ---------------- static device scratch (no allocations allowed) ------------
__device__ __half g_hh[NNODE * FOUT];     // GEMM output, fp16 mirror (10.2 MB)
__device__ float g_x2[NNODE * FOUT];      // layer-1 activated output (20.5 MB)
__device__ float g_als[NNODE * HH];       // atomic-accumulated att dots
__device__ float g_ald[NNODE * HH];
__device__ int   g_cnt[NNODE];
__device__ int   g_offs[NNODE + 1];
__device__ int   g_cursor[NNODE];
__device__ int   g_srcs[ETOT];            // dst-sorted CSR: src per slot
__device__ float g_lew[ETOT];             // dst-sorted CSR: log2(edge_weight)

// ---------------- zero init (cnt + att dot accumulators) --------------------
__global__ void k_zero() {
    int i = blockIdx.x * blockDim.x + threadIdx.x;
    if (i < NNODE * HH) { g_als[i] = 0.f; g_ald[i] = 0.f; }
    if (i < NNODE) g_cnt[i] = 0;
}

// zero only the attention-dot accumulators (between layers; NOT inside the
// aggregation kernel — other blocks still read g_als[src] there).
__global__ void k_zero_att() {
    int i = blockIdx.x * blockDim.x + threadIdx.x;
    if (i < NNODE * HH) { g_als[i] = 0.f; g_ald[i] = 0.f; }
}

__global__ void k_hist(const int* __restrict__ ei) {
    int e = blockIdx.x * blockDim.x + threadIdx.x;
    if (e >= ETOT) return;
    int d = (e < NEDGE) ? ei[NEDGE + e] : (e - NEDGE);
    atomicAdd(&g_cnt[d], 1);
}

__global__ void k_scan() {
    __shared__ int sh[1024];
    int t = threadIdx.x;
    const int CH = (NNODE + 1023) / 1024;   // 10
    int base = t * CH;
    int s = 0;
    for (int i = 0; i < CH; i++) {
        int idx = base + i;
        if (idx < NNODE) s += g_cnt[idx];
    }
    sh[t] = s;
    __syncthreads();
    for (int off = 1; off < 1024; off <<= 1) {
        int v = (t >= off) ? sh[t - off] : 0;
        __syncthreads();
        sh[t] += v;
        __syncthreads();
    }
    int run = (t == 0) ? 0 : sh[t - 1];
    for (int i = 0; i < CH; i++) {
        int idx = base + i;
        if (idx < NNODE) {
            g_offs[idx]   = run;
            g_cursor[idx] = run;
            run += g_cnt[idx];
        }
    }
    if (t == 1023) g_offs[NNODE] = run;
}

__global__ void k_scatter(const int* __restrict__ ei, const float* __restrict__ ew) {
    int e = blockIdx.x * blockDim.x + threadIdx.x;
    if (e >= ETOT) return;
    int s, d; float lw;
    if (e < NEDGE) {
        s = ei[e]; d = ei[NEDGE + e];
        lw = log2f(ew[e]);
    } else {
        s = d = e - NEDGE;
        lw = 0.f;
    }
    int pos = atomicAdd(&g_cursor[d], 1);
    g_srcs[pos] = s;
    g_lew[pos]  = lw;
}

// ---------------- 3xBF16 tensor-core GEMM + fused att-dot epilogue ----------
// C = A[M,K] @ B[K,512] via mma.m16n8k16.bf16, hi/lo split (3 products).
// h stored fp16 into g_hh; als/ald accumulated via atomicAdd from fp32 acc.
// 128x128 block tile, BK=16, double-buffered smem.
__device__ __forceinline__ uint32_t bf16x2(float odd, float even) {
    // packs: low half = bf16(even k), high half = bf16(odd k)
    uint32_t r;
    asm("cvt.rn.bf16x2.f32 %0, %1, %2;" : "=r"(r) : "f"(odd), "f"(even));
    return r;
}

__device__ __forceinline__ void split2(float even, float odd,
                                       uint32_t& H, uint32_t& L) {
    H = bf16x2(odd, even);
    float eh = __uint_as_float(H << 16);
    float oh = __uint_as_float(H & 0xffff0000u);
    L = bf16x2(odd - oh, even - eh);
}

__device__ __forceinline__ void mma_bf16(float c[4],
                                         uint32_t a0, uint32_t a1, uint32_t a2, uint32_t a3,
                                         uint32_t b0, uint32_t b1) {
    asm volatile(
        "mma.sync.aligned.m16n8k16.row.col.f32.bf16.bf16.f32 "
        "{%0,%1,%2,%3}, {%4,%5,%6,%7}, {%8,%9}, {%0,%1,%2,%3};"
        : "+f"(c[0]), "+f"(c[1]), "+f"(c[2]), "+f"(c[3])
        : "r"(a0), "r"(a1), "r"(a2), "r"(a3), "r"(b0), "r"(b1));
}

#define SPITCH 136   /* words; 136 mod 32 = 8 -> conflict-free frag LDS */

__global__ __launch_bounds__(256) void k_gemm_tc(
    const float* __restrict__ A_ext, const float* __restrict__ B,
    const float* __restrict__ att_s, const float* __restrict__ att_d,
    int M, int K, int a_internal)
{
    __shared__ uint32_t AsH[2][8][SPITCH];
    __shared__ uint32_t AsL[2][8][SPITCH];
    __shared__ uint32_t BsH[2][8][SPITCH];
    __shared__ uint32_t BsL[2][8][SPITCH];

    const float* A = a_internal ? g_x2 : A_ext;
    const int NN = FOUT;

    int bm = blockIdx.y * 128;
    int bn = blockIdx.x * 128;
    int tid  = threadIdx.x;
    int lane = tid & 31;
    int warp = tid >> 5;
    int wm = (warp & 1) * 64;   // warp row offset in block tile
    int wn = (warp >> 1) * 32;  // warp col offset in block tile

    // gmem->smem mapping. A tile 128x16 fp32: am=row, ak=k offset (0 or 8)
    int am = tid >> 1;
    int ak = (tid & 1) * 8;
    int arow = bm + am;
    // B tile 16x128 fp32: thread owns k-pair row br (k=2br,2br+1), cols bc..bc+3
    int br = tid >> 5;            // 0..7
    int bc = (tid & 31) * 4;      // 0..124

    float acc[4][4][4];
#pragma unroll
    for (int mi = 0; mi < 4; mi++)
#pragma unroll
        for (int ni = 0; ni < 4; ni++)
#pragma unroll
            for (int r = 0; r < 4; r++) acc[mi][ni][r] = 0.f;

    float4 a0v, a1v, b0v, b1v;

    auto load_tile = [&](int k0) {
        if (arow < M) {
            a0v = *(const float4*)(A + (size_t)arow * K + k0 + ak);
            a1v = *(const float4*)(A + (size_t)arow * K + k0 + ak + 4);
        } else {
            a0v = a1v = make_float4(0.f, 0.f, 0.f, 0.f);
        }
        b0v = *(const float4*)(B + (size_t)(k0 + 2 * br) * NN + bn + bc);
        b1v = *(const float4*)(B + (size_t)(k0 + 2 * br + 1) * NN + bn + bc);
    };

    auto store_tile = [&](int buf) {
        float va[8] = {a0v.x, a0v.y, a0v.z, a0v.w, a1v.x, a1v.y, a1v.z, a1v.w};
        int k2b = ak >> 1;   // 0 or 4
#pragma unroll
        for (int j = 0; j < 4; j++) {
            uint32_t H, L;
            split2(va[2 * j], va[2 * j + 1], H, L);
            AsH[buf][k2b + j][am] = H;
            AsL[buf][k2b + j][am] = L;
        }
        float ve[4] = {b0v.x, b0v.y, b0v.z, b0v.w};   // even k
        float vo[4] = {b1v.x, b1v.y, b1v.z, b1v.w};   // odd k
        uint32_t BH[4], BL[4];
#pragma unroll
        for (int j = 0; j < 4; j++) split2(ve[j], vo[j], BH[j], BL[j]);
        *(uint4*)&BsH[buf][br][bc] = make_uint4(BH[0], BH[1], BH[2], BH[3]);
        *(uint4*)&BsL[buf][br][bc] = make_uint4(BL[0], BL[1], BL[2], BL[3]);
    };

    load_tile(0);
    store_tile(0);
    __syncthreads();

    int buf = 0;
    for (int k0 = 0; k0 < K; k0 += 16) {
        bool has_next = (k0 + 16) < K;
        if (has_next) load_tile(k0 + 16);

        int fk = lane & 3;
        int fg = lane >> 2;
        uint32_t ah[4][4], al[4][4];
#pragma unroll
        for (int mi = 0; mi < 4; mi++) {
            int m0 = wm + mi * 16 + fg;
            ah[mi][0] = AsH[buf][fk][m0];      ah[mi][1] = AsH[buf][fk][m0 + 8];
            ah[mi][2] = AsH[buf][fk + 4][m0];  ah[mi][3] = AsH[buf][fk + 4][m0 + 8];
            al[mi][0] = AsL[buf][fk][m0];      al[mi][1] = AsL[buf][fk][m0 + 8];
            al[mi][2] = AsL[buf][fk + 4][m0];  al[mi][3] = AsL[buf][fk + 4][m0 + 8];
        }
        uint32_t bh[4][2], bl[4][2];
#pragma unroll
        for (int ni = 0; ni < 4; ni++) {
            int n0 = wn + ni * 8 + fg;
            bh[ni][0] = BsH[buf][fk][n0];      bh[ni][1] = BsH[buf][fk + 4][n0];
            bl[ni][0] = BsL[buf][fk][n0];      bl[ni][1] = BsL[buf][fk + 4][n0];
        }

#pragma unroll
        for (int mi = 0; mi < 4; mi++)
#pragma unroll
            for (int ni = 0; ni < 4; ni++) {
                mma_bf16(acc[mi][ni], ah[mi][0], ah[mi][1], ah[mi][2], ah[mi][3],
                         bh[ni][0], bh[ni][1]);
                mma_bf16(acc[mi][ni], ah[mi][0], ah[mi][1], ah[mi][2], ah[mi][3],
                         bl[ni][0], bl[ni][1]);
                mma_bf16(acc[mi][ni], al[mi][0], al[mi][1], al[mi][2], al[mi][3],
                         bh[ni][0], bh[ni][1]);
            }

        if (has_next) store_tile(buf ^ 1);
        __syncthreads();
        buf ^= 1;
    }

    // ---- epilogue: fp16 store + fused att dot products ----
    int fg = lane >> 2;
    int fk = lane & 3;
    int headg = (bn + wn) >> 6;   // warp's 32 cols lie in exactly one head

    float vsv[4][2], vdv[4][2];
#pragma unroll
    for (int ni = 0; ni < 4; ni++) {
        int c = bn + wn + ni * 8 + fk * 2;
        vsv[ni][0] = att_s[c]; vsv[ni][1] = att_s[c + 1];
        vdv[ni][0] = att_d[c]; vdv[ni][1] = att_d[c + 1];
    }

#pragma unroll
    for (int mi = 0; mi < 4; mi++) {
        int r0 = bm + wm + mi * 16 + fg;
        int r1 = r0 + 8;
        float s0 = 0.f, d0 = 0.f, s1 = 0.f, d1 = 0.f;
#pragma unroll
        for (int ni = 0; ni < 4; ni++) {
            int col = bn + wn + ni * 8 + fk * 2;
            __half2 h01 = __floats2half2_rn(acc[mi][ni][0], acc[mi][ni][1]);
            __half2 h23 = __floats2half2_rn(acc[mi][ni][2], acc[mi][ni][3]);
            if (r0 < M) *(__half2*)(g_hh + (size_t)r0 * NN + col) = h01;
            if (r1 < M) *(__half2*)(g_hh + (size_t)r1 * NN + col) = h23;
            s0 += acc[mi][ni][0] * vsv[ni][0] + acc[mi][ni][1] * vsv[ni][1];
            d0 += acc[mi][ni][0] * vdv[ni][0] + acc[mi][ni][1] * vdv[ni][1];
            s1 += acc[mi][ni][2] * vsv[ni][0] + acc[mi][ni][3] * vsv[ni][1];
            d1 += acc[mi][ni][2] * vdv[ni][0] + acc[mi][ni][3] * vdv[ni][1];
        }
#pragma unroll
        for (int off = 2; off; off >>= 1) {
            s0 += __shfl_xor_sync(0xffffffffu, s0, off);
            d0 += __shfl_xor_sync(0xffffffffu, d0, off);
            s1 += __shfl_xor_sync(0xffffffffu, s1, off);
            d1 += __shfl_xor_sync(0xffffffffu, d1, off);
        }
        if (fk == 0) {
            if (r0 < M) {
                atomicAdd(&g_als[r0 * HH + headg], s0);
                atomicAdd(&g_ald[r0 * HH + headg], d0);
            }
            if (r1 < M) {
                atomicAdd(&g_als[r1 * HH + headg], s1);
                atomicAdd(&g_ald[r1 * HH + headg], d1);
            }
        }
    }
}

// ------------- fused flash softmax + aggregation: warp = (node, head) -------
// online (max, sum, rescaled accumulator); recomputes alpha from als/ald/lew.
// NOTE: must NOT zero g_als/g_ald here — other blocks concurrently read
// g_als[src] for their edges (caused the round-4 0.19 rel_err race).
__global__ void k_fusedagg(const float* __restrict__ bias,
                           float* __restrict__ out_ext, int do_relu)
{
    int n = blockIdx.x;
    int w = threadIdx.x >> 5, lane = threadIdx.x & 31;
    float* out = out_ext ? out_ext : g_x2;
    int s0 = g_offs[n], s1 = g_offs[n + 1];

    float adw = g_ald[n * HH + w];
    float m = -1e30f, ssum = 0.f, accx = 0.f, accy = 0.f;

    for (int base = s0; base < s1; base += 32) {
        int idx = base + lane;
        bool valid = idx < s1;
        int mys = valid ? g_srcs[idx] : 0;
        float t = -1e30f;
        if (valid) {
            float a = g_als[mys * HH + w] + adw;
            a = (a > 0.f) ? a : NEG * a;   // leaky_relu
            t = a + g_lew[idx];
        }
        // chunk max -> running max with rescale
        float cm = t;
#pragma unroll
        for (int o = 16; o; o >>= 1)
            cm = fmaxf(cm, __shfl_xor_sync(0xffffffffu, cm, o));
        float mnew = fmaxf(m, cm);
        float scale = __expf(m - mnew);
        ssum *= scale; accx *= scale; accy *= scale;
        m = mnew;

        float e = __expf(t - mnew);   // 0 for invalid lanes
        ssum += e;

        int cnt = min(32, s1 - base);
        for (int j = 0; j < cnt; j++) {
            int   s  = __shfl_sync(0xffffffffu, mys, j);
            float wv = __shfl_sync(0xffffffffu, e, j);
            float2 hv = __half22float2(
                *(const __half2*)(g_hh + (size_t)s * FOUT + w * CC + lane * 2));
            accx = fmaf(wv, hv.x, accx);
            accy = fmaf(wv, hv.y, accy);
        }
    }
#pragma unroll
    for (int o = 16; o; o >>= 1)
        ssum += __shfl_xor_sync(0xffffffffu, ssum, o);

    float r = 1.f / ssum;
    float2 b = *(const float2*)(bias + w * CC + lane * 2);
    float ox = fmaf(accx, r, b.x);
    float oy = fmaf(accy, r, b.y);
    if (do_relu) { ox = fmaxf(ox, 0.f); oy = fmaxf(oy, 0.f); }
    *(float2*)(out + (size_t)n * FOUT + w * CC + lane * 2) = make_float2(ox, oy);
}

// ---------------- launch -----------------------------------------------------
extern "C" void kernel_launch(void* const* d_in, const int* in_sizes, int n_in,
                              void* d_out, int out_size)
{
    const float* x   = (const float*)d_in[0];
    const int*   ei  = (const int*)  d_in[1];
    const float* ew  = (const float*)d_in[2];
    const float* W1  = (const float*)d_in[3];
    const float* as1 = (const float*)d_in[4];
    const float* ad1 = (const float*)d_in[5];
    const float* b1  = (const float*)d_in[6];
    const float* W2  = (const float*)d_in[7];
    const float* as2 = (const float*)d_in[8];
    const float* ad2 = (const float*)d_in[9];
    const float* b2  = (const float*)d_in[10];
    float* out = (float*)d_out;

    // CSR build + zero (shared by both layers)
    k_zero<<<(NNODE * HH + 255) / 256, 256>>>();
    k_hist<<<(ETOT + 255) / 256, 256>>>(ei);
    k_scan<<<1, 1024>>>();
    k_scatter<<<(ETOT + 255) / 256, 256>>>(ei, ew);

    dim3 ggrid(FOUT / 128, (NNODE + 127) / 128);

    // layer 1
    k_gemm_tc<<<ggrid, 256>>>(x, W1, as1, ad1, NNODE, FIN, 0);
    k_fusedagg<<<NNODE, 256>>>(b1, nullptr, 1);       // -> g_x2 with ReLU

    // zero att accumulators AFTER all reads of layer-1 als/ald are done
    k_zero_att<<<(NNODE * HH + 255) / 256, 256>>>();

    // layer 2
    k_gemm_tc<<<ggrid, 256>>>(nullptr, W2, as2, ad2, NNODE, FOUT, 1);
    k_fusedagg<<<NNODE, 256>>>(b2, out, 0);           // -> d_out, no ReLU
}